// round 4
// baseline (speedup 1.0000x reference)
#include <cuda_runtime.h>
#include <cuda_bf16.h>
#include <cfloat>
#include <math.h>

// ---------------- problem constants ----------------
#define N_NODES   20000
#define N_EDGES   160000
#define N_IN      300
#define NHID      128
#define HEADS     4
#define NOUT      768
#define NUM_GRAPHS 128

typedef unsigned long long ull;

// ---------------- scratch ----------------
__device__ float g_h0[N_NODES * NHID];
__device__ float g_f1[N_NODES * HEADS * NHID];
__device__ float g_o1[N_NODES * HEADS * NHID];
__device__ float g_f2[N_NODES * NHID];
__device__ float g_o2[N_NODES * NHID];
__device__ float g_aldot[N_NODES * HEADS];
__device__ float g_ardot[N_NODES * HEADS];
__device__ int   g_deg[N_NODES];
__device__ int   g_rowptr[N_NODES + 1];
__device__ int   g_cursor[N_NODES];
__device__ int   g_esrc[N_EDGES];
__device__ float g_pool[NUM_GRAPHS * NHID];

// ---------------- packed f32x2 helpers ----------------
__device__ __forceinline__ void fma2(ull& d, ull a, ull b) {
    asm("fma.rn.f32x2 %0, %1, %2, %0;" : "+l"(d) : "l"(a), "l"(b));
}
__device__ __forceinline__ ull pack2(float x, float y) {
    ull r; asm("mov.b64 %0, {%1, %2};" : "=l"(r) : "f"(x), "f"(y)); return r;
}
__device__ __forceinline__ void unpack2(ull v, float& x, float& y) {
    asm("mov.b64 {%0, %1}, %2;" : "=f"(x), "=f"(y) : "l"(v));
}

// ---------------- CSR build ----------------
__global__ void zero_int_kernel(int* p, int n) {
    int i = blockIdx.x * blockDim.x + threadIdx.x;
    if (i < n) p[i] = 0;
}

__global__ void hist_kernel(const int* __restrict__ dst, int* __restrict__ deg, int E) {
    int i = blockIdx.x * blockDim.x + threadIdx.x;
    if (i < E) atomicAdd(&deg[dst[i]], 1);
}

__global__ void scan_kernel(const int* __restrict__ deg, int* __restrict__ rowptr,
                            int* __restrict__ cursor) {
    __shared__ int sh[1024];
    const int PER = 20;
    int tid = threadIdx.x;
    int base = tid * PER;
    int loc[PER];
    int s = 0;
    #pragma unroll
    for (int i = 0; i < PER; i++) {
        int idx = base + i;
        int v = (idx < N_NODES) ? deg[idx] : 0;
        loc[i] = s;
        s += v;
    }
    sh[tid] = s;
    __syncthreads();
    #pragma unroll
    for (int off = 1; off < 1024; off <<= 1) {
        int t = (tid >= off) ? sh[tid - off] : 0;
        __syncthreads();
        sh[tid] += t;
        __syncthreads();
    }
    int prev = (tid > 0) ? sh[tid - 1] : 0;
    #pragma unroll
    for (int i = 0; i < PER; i++) {
        int idx = base + i;
        if (idx < N_NODES) {
            int v = prev + loc[i];
            rowptr[idx] = v;
            cursor[idx] = v;
        }
    }
    if (tid == 1023) rowptr[N_NODES] = sh[1023];
}

__global__ void scatter_kernel(const int* __restrict__ src, const int* __restrict__ dst,
                               int* __restrict__ cursor, int* __restrict__ esrc, int E) {
    int i = blockIdx.x * blockDim.x + threadIdx.x;
    if (i < E) {
        int d = dst[i];
        int p = atomicAdd(&cursor[d], 1);
        esrc[p] = src[i];
    }
}

// ---------------- f32x2 GEMM: 128x128 tile, 128 threads, 16x8 per thread ----------------
// Double-buffered smem, register prefetch, zero-filled K tail.
__global__ __launch_bounds__(128, 2)
void gemm2x_kernel(const float* __restrict__ A, const float* __restrict__ B,
                   const float* __restrict__ bias, float* __restrict__ C,
                   int M, int N, int K, float slope, int act) {
    const int BM = 128, BN = 128, BK = 16;
    __shared__ float As[2][BK][BM];
    __shared__ float Bs[2][BK][BN];

    int tid = threadIdx.x;             // 128 threads
    int bm = blockIdx.y * BM, bn = blockIdx.x * BN;
    int tx = tid & 15;                 // N: cols tx*4..+3 and 64+tx*4..+3
    int ty = tid >> 4;                 // M: rows ty*16..+15 (ty 0..7)

    // loaders: A -> 1 row/thread, 16 k-values; B -> 1 k-row segment of 16 n/thread
    int gm_a = bm + tid;
    int lb_k = tid >> 3;               // 0..15
    int lb_n = (tid & 7) * 16;         // 0..112

    float4 pa[4], pb[4];

    ull acc[16][4];
    #pragma unroll
    for (int i = 0; i < 16; i++)
        #pragma unroll
        for (int j = 0; j < 4; j++) acc[i][j] = pack2(0.f, 0.f);

    int nT = (K + BK - 1) / BK;

    // prologue: prefetch tile 0
    {
        #pragma unroll
        for (int g = 0; g < 4; g++) {
            int gk = g * 4;
            float4 v = make_float4(0.f, 0.f, 0.f, 0.f);
            if (gm_a < M && gk < K) v = *reinterpret_cast<const float4*>(&A[(size_t)gm_a * K + gk]);
            pa[g] = v;
        }
        #pragma unroll
        for (int g = 0; g < 4; g++) {
            float4 v = make_float4(0.f, 0.f, 0.f, 0.f);
            if (lb_k < K) v = *reinterpret_cast<const float4*>(&B[(size_t)lb_k * N + bn + lb_n + g * 4]);
            pb[g] = v;
        }
        #pragma unroll
        for (int g = 0; g < 4; g++) {
            As[0][g * 4 + 0][tid] = pa[g].x;
            As[0][g * 4 + 1][tid] = pa[g].y;
            As[0][g * 4 + 2][tid] = pa[g].z;
            As[0][g * 4 + 3][tid] = pa[g].w;
            *reinterpret_cast<float4*>(&Bs[0][lb_k][lb_n + g * 4]) = pb[g];
        }
    }
    __syncthreads();

    for (int t = 0; t < nT; t++) {
        int buf = t & 1;
        bool more = (t + 1) < nT;
        if (more) {
            int k0 = (t + 1) * BK;
            #pragma unroll
            for (int g = 0; g < 4; g++) {
                int gk = k0 + g * 4;
                float4 v = make_float4(0.f, 0.f, 0.f, 0.f);
                if (gm_a < M && gk < K) v = *reinterpret_cast<const float4*>(&A[(size_t)gm_a * K + gk]);
                pa[g] = v;
            }
            int gk = k0 + lb_k;
            #pragma unroll
            for (int g = 0; g < 4; g++) {
                float4 v = make_float4(0.f, 0.f, 0.f, 0.f);
                if (gk < K) v = *reinterpret_cast<const float4*>(&B[(size_t)gk * N + bn + lb_n + g * 4]);
                pb[g] = v;
            }
        }

        #pragma unroll
        for (int k = 0; k < BK; k++) {
            float4 b0 = *reinterpret_cast<const float4*>(&Bs[buf][k][tx * 4]);
            float4 b1 = *reinterpret_cast<const float4*>(&Bs[buf][k][64 + tx * 4]);
            ull bp0 = pack2(b0.x, b0.y), bp1 = pack2(b0.z, b0.w);
            ull bp2 = pack2(b1.x, b1.y), bp3 = pack2(b1.z, b1.w);
            #pragma unroll
            for (int i = 0; i < 16; i += 4) {
                float4 a = *reinterpret_cast<const float4*>(&As[buf][k][ty * 16 + i]);
                ull ap;
                ap = pack2(a.x, a.x);
                fma2(acc[i + 0][0], ap, bp0); fma2(acc[i + 0][1], ap, bp1);
                fma2(acc[i + 0][2], ap, bp2); fma2(acc[i + 0][3], ap, bp3);
                ap = pack2(a.y, a.y);
                fma2(acc[i + 1][0], ap, bp0); fma2(acc[i + 1][1], ap, bp1);
                fma2(acc[i + 1][2], ap, bp2); fma2(acc[i + 1][3], ap, bp3);
                ap = pack2(a.z, a.z);
                fma2(acc[i + 2][0], ap, bp0); fma2(acc[i + 2][1], ap, bp1);
                fma2(acc[i + 2][2], ap, bp2); fma2(acc[i + 2][3], ap, bp3);
                ap = pack2(a.w, a.w);
                fma2(acc[i + 3][0], ap, bp0); fma2(acc[i + 3][1], ap, bp1);
                fma2(acc[i + 3][2], ap, bp2); fma2(acc[i + 3][3], ap, bp3);
            }
        }

        if (more) {
            int nbuf = 1 - buf;
            #pragma unroll
            for (int g = 0; g < 4; g++) {
                As[nbuf][g * 4 + 0][tid] = pa[g].x;
                As[nbuf][g * 4 + 1][tid] = pa[g].y;
                As[nbuf][g * 4 + 2][tid] = pa[g].z;
                As[nbuf][g * 4 + 3][tid] = pa[g].w;
                *reinterpret_cast<float4*>(&Bs[nbuf][lb_k][lb_n + g * 4]) = pb[g];
            }
            __syncthreads();
        }
    }

    // epilogue
    int gn0 = bn + tx * 4;
    int gn1 = bn + 64 + tx * 4;
    float bias0[4], bias1[4];
    if (bias) {
        #pragma unroll
        for (int j = 0; j < 4; j++) { bias0[j] = bias[gn0 + j]; bias1[j] = bias[gn1 + j]; }
    } else {
        #pragma unroll
        for (int j = 0; j < 4; j++) { bias0[j] = 0.f; bias1[j] = 0.f; }
    }
    #pragma unroll
    for (int i = 0; i < 16; i++) {
        int gm = bm + ty * 16 + i;
        if (gm >= M) continue;
        float c[8];
        #pragma unroll
        for (int j = 0; j < 4; j++) unpack2(acc[i][j], c[2 * j], c[2 * j + 1]);
        #pragma unroll
        for (int j = 0; j < 4; j++) { c[j] += bias0[j]; c[4 + j] += bias1[j]; }
        if (act) {
            #pragma unroll
            for (int j = 0; j < 8; j++) c[j] = c[j] > 0.f ? c[j] : slope * c[j];
        }
        *reinterpret_cast<float4*>(&C[(size_t)gm * N + gn0]) = make_float4(c[0], c[1], c[2], c[3]);
        *reinterpret_cast<float4*>(&C[(size_t)gm * N + gn1]) = make_float4(c[4], c[5], c[6], c[7]);
    }
}

// ---------------- precompute attention dots ----------------
template<int H>
__global__ void attdot_kernel(const float* __restrict__ feat,
                              const float* __restrict__ attL, const float* __restrict__ attR,
                              float* __restrict__ aldot, float* __restrict__ ardot) {
    int warp = (blockIdx.x * blockDim.x + threadIdx.x) >> 5;
    int lane = threadIdx.x & 31;
    if (warp >= N_NODES * H) return;
    int nid = warp / H, h = warp % H;
    float4 x = reinterpret_cast<const float4*>(feat + ((size_t)nid * H + h) * NHID)[lane];
    float4 aL = reinterpret_cast<const float4*>(attL + h * NHID)[lane];
    float4 aR = reinterpret_cast<const float4*>(attR + h * NHID)[lane];
    float al = x.x * aL.x + x.y * aL.y + x.z * aL.z + x.w * aL.w;
    float ar = x.x * aR.x + x.y * aR.y + x.z * aR.z + x.w * aR.w;
    #pragma unroll
    for (int o = 16; o; o >>= 1) {
        al += __shfl_xor_sync(0xffffffffu, al, o);
        ar += __shfl_xor_sync(0xffffffffu, ar, o);
    }
    if (lane == 0) { aldot[warp] = al; ardot[warp] = ar; }
}

// ---------------- SuperGAT aggregation ----------------
template<int H>
__global__ void agg_kernel(const float* __restrict__ feat,
                           const float* __restrict__ aldot, const float* __restrict__ ardot,
                           const float* __restrict__ bias,
                           const int* __restrict__ rowptr, const int* __restrict__ esrc,
                           float* __restrict__ out, float out_slope) {
    const int C = NHID;
    int warp = (blockIdx.x * blockDim.x + threadIdx.x) >> 5;
    int lane = threadIdx.x & 31;
    if (warp >= N_NODES * H) return;
    int nid = warp / H;
    int h   = warp % H;

    float4 xi = reinterpret_cast<const float4*>(feat + ((size_t)nid * H + h) * C)[lane];
    float ar = ardot[warp];

    float m = -INFINITY, s = 0.f;
    float4 acc = make_float4(0.f, 0.f, 0.f, 0.f);

    int e0 = rowptr[nid], e1 = rowptr[nid + 1];
    int e = e0;
    for (; e + 1 < e1; e += 2) {
        int s1 = esrc[e], s2 = esrc[e + 1];
        float4 xj1 = reinterpret_cast<const float4*>(feat + ((size_t)s1 * H + h) * C)[lane];
        float4 xj2 = reinterpret_cast<const float4*>(feat + ((size_t)s2 * H + h) * C)[lane];
        float lg1 = xi.x * xj1.x + xi.y * xj1.y + xi.z * xj1.z + xi.w * xj1.w;
        float lg2 = xi.x * xj2.x + xi.y * xj2.y + xi.z * xj2.z + xi.w * xj2.w;
        #pragma unroll
        for (int o = 16; o; o >>= 1) {
            lg1 += __shfl_xor_sync(0xffffffffu, lg1, o);
            lg2 += __shfl_xor_sync(0xffffffffu, lg2, o);
        }
        float al1 = aldot[s1 * H + h], al2 = aldot[s2 * H + h];
        float a1 = (al1 + ar) * (1.f / (1.f + expf(-lg1)));
        float a2 = (al2 + ar) * (1.f / (1.f + expf(-lg2)));
        a1 = a1 > 0.f ? a1 : 0.2f * a1;
        a2 = a2 > 0.f ? a2 : 0.2f * a2;
        float mn = fmaxf(m, fmaxf(a1, a2));
        float scale = expf(m - mn);
        float w1 = expf(a1 - mn), w2 = expf(a2 - mn);
        s = s * scale + w1 + w2;
        acc.x = acc.x * scale + w1 * xj1.x + w2 * xj2.x;
        acc.y = acc.y * scale + w1 * xj1.y + w2 * xj2.y;
        acc.z = acc.z * scale + w1 * xj1.z + w2 * xj2.z;
        acc.w = acc.w * scale + w1 * xj1.w + w2 * xj2.w;
        m = mn;
    }
    for (; e < e1; e++) {
        int sn = esrc[e];
        float4 xj = reinterpret_cast<const float4*>(feat + ((size_t)sn * H + h) * C)[lane];
        float lg = xi.x * xj.x + xi.y * xj.y + xi.z * xj.z + xi.w * xj.w;
        #pragma unroll
        for (int o = 16; o; o >>= 1) lg += __shfl_xor_sync(0xffffffffu, lg, o);
        float al = aldot[sn * H + h];
        float a = (al + ar) * (1.f / (1.f + expf(-lg)));
        a = a > 0.f ? a : 0.2f * a;
        float mn = fmaxf(m, a);
        float scale = expf(m - mn);
        float w = expf(a - mn);
        s = s * scale + w;
        acc.x = acc.x * scale + w * xj.x;
        acc.y = acc.y * scale + w * xj.y;
        acc.z = acc.z * scale + w * xj.z;
        acc.w = acc.w * scale + w * xj.w;
        m = mn;
    }
    float inv = 1.f / (s + 1e-16f);
    float4 b4 = reinterpret_cast<const float4*>(bias + h * C)[lane];
    float4 r;
    r.x = acc.x * inv + b4.x; r.x = r.x > 0.f ? r.x : out_slope * r.x;
    r.y = acc.y * inv + b4.y; r.y = r.y > 0.f ? r.y : out_slope * r.y;
    r.z = acc.z * inv + b4.z; r.z = r.z > 0.f ? r.z : out_slope * r.z;
    r.w = acc.w * inv + b4.w; r.w = r.w > 0.f ? r.w : out_slope * r.w;
    reinterpret_cast<float4*>(out + ((size_t)nid * H + h) * C)[lane] = r;
}

// ---------------- graph pooling ----------------
__global__ void pool_init_kernel(float* pool) {
    int i = blockIdx.x * blockDim.x + threadIdx.x;
    if (i < NUM_GRAPHS * NHID) pool[i] = -FLT_MAX;
}

__device__ __forceinline__ void atomicMaxF(float* a, float v) {
    if (v >= 0.f) atomicMax((int*)a, __float_as_int(v));
    else          atomicMin((unsigned int*)a, __float_as_uint(v));
}

__global__ void pool_max_kernel(const float* __restrict__ x, const int* __restrict__ batch,
                                float* __restrict__ pool) {
    int i = blockIdx.x * blockDim.x + threadIdx.x;
    if (i >= N_NODES * NHID) return;
    int n = i / NHID, c = i % NHID;
    atomicMaxF(&pool[batch[n] * NHID + c], x[i]);
}

// ---------------- launch ----------------
static inline float* symf(const void* sym) {
    void* p = nullptr; cudaGetSymbolAddress(&p, sym); return (float*)p;
}
static inline int* symi(const void* sym) {
    void* p = nullptr; cudaGetSymbolAddress(&p, sym); return (int*)p;
}

extern "C" void kernel_launch(void* const* d_in, const int* in_sizes, int n_in,
                              void* d_out, int out_size) {
    const float* x      = (const float*)d_in[0];
    const int*   eidx   = (const int*)  d_in[1];
    const int*   batch  = (const int*)  d_in[2];
    const float* fc1_w  = (const float*)d_in[3];
    const float* fc1_b  = (const float*)d_in[4];
    const float* w1     = (const float*)d_in[5];
    const float* att_l1 = (const float*)d_in[6];
    const float* att_r1 = (const float*)d_in[7];
    const float* b1     = (const float*)d_in[8];
    const float* w2     = (const float*)d_in[9];
    const float* att_l2 = (const float*)d_in[10];
    const float* att_r2 = (const float*)d_in[11];
    const float* b2     = (const float*)d_in[12];
    const float* fc2_w  = (const float*)d_in[13];
    const float* fc2_b  = (const float*)d_in[14];
    float* out = (float*)d_out;

    const int* e_src = eidx;
    const int* e_dst = eidx + N_EDGES;

    float* h0 = symf(g_h0); float* f1 = symf(g_f1); float* o1 = symf(g_o1);
    float* f2 = symf(g_f2); float* o2 = symf(g_o2); float* pool = symf(g_pool);
    float* aldot = symf(g_aldot); float* ardot = symf(g_ardot);
    int* deg = symi(g_deg); int* rowptr = symi(g_rowptr);
    int* cursor = symi(g_cursor); int* esrc = symi(g_esrc);

    zero_int_kernel<<<(N_NODES + 255) / 256, 256>>>(deg, N_NODES);                     // 0
    hist_kernel<<<(N_EDGES + 255) / 256, 256>>>(e_dst, deg, N_EDGES);                  // 1

    // GEMM1: h0 = leaky(x @ fc1_w + fc1_b)
    {
        dim3 grid(NHID / 128, (N_NODES + 127) / 128);
        gemm2x_kernel<<<grid, 128>>>(x, fc1_w, fc1_b, h0, N_NODES, NHID, N_IN, 0.01f, 1); // 2
    }
    // GEMM2: f1 = h0 @ w1   (profiled slot 3)
    {
        dim3 grid(HEADS * NHID / 128, (N_NODES + 127) / 128);
        gemm2x_kernel<<<grid, 128>>>(h0, w1, nullptr, f1, N_NODES, HEADS * NHID, NHID, 0.f, 0); // 3
    }

    scan_kernel<<<1, 1024>>>(deg, rowptr, cursor);                                     // 4
    scatter_kernel<<<(N_EDGES + 255) / 256, 256>>>(e_src, e_dst, cursor, esrc, N_EDGES); // 5

    {
        int warps = N_NODES * HEADS;
        attdot_kernel<HEADS><<<(warps * 32 + 255) / 256, 256>>>(f1, att_l1, att_r1, aldot, ardot); // 6
    }
    {
        int warps = N_NODES * HEADS;
        agg_kernel<HEADS><<<(warps * 32 + 255) / 256, 256>>>(f1, aldot, ardot, b1,
                                                             rowptr, esrc, o1, 0.01f); // 7
    }
    // GEMM3: f2 = o1 @ w2
    {
        dim3 grid(NHID / 128, (N_NODES + 127) / 128);
        gemm2x_kernel<<<grid, 128>>>(o1, w2, nullptr, f2, N_NODES, NHID, HEADS * NHID, 0.f, 0); // 8
    }
    {
        int warps = N_NODES;
        attdot_kernel<1><<<(warps * 32 + 255) / 256, 256>>>(f2, att_l2, att_r2, aldot, ardot); // 9
    }
    {
        int warps = N_NODES;
        agg_kernel<1><<<(warps * 32 + 255) / 256, 256>>>(f2, aldot, ardot, b2,
                                                         rowptr, esrc, o2, 0.01f);     // 10
    }
    pool_init_kernel<<<(NUM_GRAPHS * NHID + 255) / 256, 256>>>(pool);                  // 11
    pool_max_kernel<<<(N_NODES * NHID + 255) / 256, 256>>>(o2, batch, pool);           // 12

    // GEMM4
    {
        dim3 grid(NOUT / 128, (NUM_GRAPHS + 127) / 128);
        gemm2x_kernel<<<grid, 128>>>(pool, fc2_w, fc2_b, out, NUM_GRAPHS, NOUT, NHID, 0.f, 0); // 13
    }
}

// round 6
// speedup vs baseline: 1.1525x; 1.1525x over previous
#include <cuda_runtime.h>
#include <cuda_bf16.h>
#include <cfloat>
#include <math.h>

// ---------------- problem constants ----------------
#define N_NODES   20000
#define N_EDGES   160000
#define N_IN      300
#define NHID      128
#define HEADS     4
#define NOUT      768
#define NUM_GRAPHS 128

typedef unsigned long long ull;

// ---------------- scratch ----------------
__device__ float g_h0[N_NODES * NHID];
__device__ float g_f1[N_NODES * HEADS * NHID];
__device__ float g_o1[N_NODES * HEADS * NHID];
__device__ float g_f2[N_NODES * NHID];
__device__ float g_o2[N_NODES * NHID];
__device__ float g_aldot[N_NODES * HEADS];
__device__ float g_ardot[N_NODES * HEADS];
__device__ int   g_deg[N_NODES];
__device__ int   g_rowptr[N_NODES + 1];
__device__ int   g_cursor[N_NODES];
__device__ int   g_esrc[N_EDGES];
__device__ float g_pool[NUM_GRAPHS * NHID];

// ---------------- packed f32x2 helpers ----------------
__device__ __forceinline__ void fma2(ull& d, ull a, ull b) {
    asm("fma.rn.f32x2 %0, %1, %2, %0;" : "+l"(d) : "l"(a), "l"(b));
}
__device__ __forceinline__ ull pack2(float x, float y) {
    ull r; asm("mov.b64 %0, {%1, %2};" : "=l"(r) : "f"(x), "f"(y)); return r;
}
__device__ __forceinline__ void unpack2(ull v, float& x, float& y) {
    asm("mov.b64 {%0, %1}, %2;" : "=f"(x), "=f"(y) : "l"(v));
}

// ---------------- CSR build ----------------
__global__ void zero_int_kernel(int* p, int n) {
    int i = blockIdx.x * blockDim.x + threadIdx.x;
    if (i < n) p[i] = 0;
}

__global__ void hist_kernel(const int* __restrict__ dst, int* __restrict__ deg, int E) {
    int i = blockIdx.x * blockDim.x + threadIdx.x;
    if (i < E) atomicAdd(&deg[dst[i]], 1);
}

__global__ void scan_kernel(const int* __restrict__ deg, int* __restrict__ rowptr,
                            int* __restrict__ cursor) {
    __shared__ int sh[1024];
    const int PER = 20;
    int tid = threadIdx.x;
    int base = tid * PER;
    int loc[PER];
    int s = 0;
    #pragma unroll
    for (int i = 0; i < PER; i++) {
        int idx = base + i;
        int v = (idx < N_NODES) ? deg[idx] : 0;
        loc[i] = s;
        s += v;
    }
    sh[tid] = s;
    __syncthreads();
    #pragma unroll
    for (int off = 1; off < 1024; off <<= 1) {
        int t = (tid >= off) ? sh[tid - off] : 0;
        __syncthreads();
        sh[tid] += t;
        __syncthreads();
    }
    int prev = (tid > 0) ? sh[tid - 1] : 0;
    #pragma unroll
    for (int i = 0; i < PER; i++) {
        int idx = base + i;
        if (idx < N_NODES) {
            int v = prev + loc[i];
            rowptr[idx] = v;
            cursor[idx] = v;
        }
    }
    if (tid == 1023) rowptr[N_NODES] = sh[1023];
}

__global__ void scatter_kernel(const int* __restrict__ src, const int* __restrict__ dst,
                               int* __restrict__ cursor, int* __restrict__ esrc, int E) {
    int i = blockIdx.x * blockDim.x + threadIdx.x;
    if (i < E) {
        int d = dst[i];
        int p = atomicAdd(&cursor[d], 1);
        esrc[p] = src[i];
    }
}

// ---------------- f32x2 tiled GEMM, templated tile (R3-proven inner loop) ----------------
// BN must be 128. Thread tile 8x8. THREADS = (BM/8)*(BN/8).
// Requires K % 4 == 0, N % BN == 0.
template<int BM, int BN>
__global__ __launch_bounds__((BM / 8) * (BN / 8))
void gemm2x_kernel(const float* __restrict__ A, const float* __restrict__ B,
                   const float* __restrict__ bias, float* __restrict__ C,
                   int M, int N, int K, float slope, int act) {
    const int BK = 16, TM = 8;
    const int THREADS = (BM / 8) * (BN / 8);
    __shared__ float As[BK][BM];
    __shared__ float Bs[BK][BN];

    int tid = threadIdx.x;
    int bm = blockIdx.y * BM, bn = blockIdx.x * BN;
    int tx = tid & 15;       // N direction: cols tx*4..+3 and 64+tx*4..+3
    int ty = tid >> 4;       // M direction: rows ty*8..+7

    // A loader: each thread loads 8 consecutive K-values of one row.
    int la_m = tid % BM;
    int la_k = (tid / BM) * 8;
    // B loader: rows strided by THREADS/32
    int lb_k0 = tid >> 5;
    const int LB_STEP = THREADS / 32;
    int lb_n = (tid & 31) * 4;

    ull acc[TM][4];
    #pragma unroll
    for (int i = 0; i < TM; i++)
        #pragma unroll
        for (int j = 0; j < 4; j++) acc[i][j] = pack2(0.f, 0.f);

    int gm_a = bm + la_m;
    for (int k0 = 0; k0 < K; k0 += BK) {
        #pragma unroll
        for (int g = 0; g < 8; g += 4) {
            int gk = k0 + la_k + g;
            float4 v = make_float4(0.f, 0.f, 0.f, 0.f);
            if (gm_a < M && gk < K)
                v = *reinterpret_cast<const float4*>(&A[(size_t)gm_a * K + gk]);
            As[la_k + g + 0][la_m] = v.x;
            As[la_k + g + 1][la_m] = v.y;
            As[la_k + g + 2][la_m] = v.z;
            As[la_k + g + 3][la_m] = v.w;
        }
        #pragma unroll
        for (int r = 0; r < BK / LB_STEP; r++) {
            int k = lb_k0 + r * LB_STEP;
            int gk = k0 + k;
            float4 v = make_float4(0.f, 0.f, 0.f, 0.f);
            if (gk < K)
                v = *reinterpret_cast<const float4*>(&B[(size_t)gk * N + bn + lb_n]);
            *reinterpret_cast<float4*>(&Bs[k][lb_n]) = v;
        }
        __syncthreads();

        #pragma unroll
        for (int k = 0; k < BK; k++) {
            float4 a0 = *reinterpret_cast<const float4*>(&As[k][ty * TM]);
            float4 a1 = *reinterpret_cast<const float4*>(&As[k][ty * TM + 4]);
            float4 b0 = *reinterpret_cast<const float4*>(&Bs[k][tx * 4]);
            float4 b1 = *reinterpret_cast<const float4*>(&Bs[k][64 + tx * 4]);
            ull bp[4];
            bp[0] = pack2(b0.x, b0.y);
            bp[1] = pack2(b0.z, b0.w);
            bp[2] = pack2(b1.x, b1.y);
            bp[3] = pack2(b1.z, b1.w);
            float av[8] = {a0.x, a0.y, a0.z, a0.w, a1.x, a1.y, a1.z, a1.w};
            #pragma unroll
            for (int i = 0; i < TM; i++) {
                ull ap = pack2(av[i], av[i]);
                #pragma unroll
                for (int j = 0; j < 4; j++) fma2(acc[i][j], ap, bp[j]);
            }
        }
        __syncthreads();
    }

    int gn0 = bn + tx * 4;
    int gn1 = bn + 64 + tx * 4;
    #pragma unroll
    for (int i = 0; i < TM; i++) {
        int gm = bm + ty * TM + i;
        if (gm >= M) continue;
        float c[8];
        #pragma unroll
        for (int j = 0; j < 4; j++) unpack2(acc[i][j], c[2 * j], c[2 * j + 1]);
        if (bias) {
            #pragma unroll
            for (int j = 0; j < 4; j++) { c[j] += bias[gn0 + j]; c[4 + j] += bias[gn1 + j]; }
        }
        if (act) {
            #pragma unroll
            for (int j = 0; j < 8; j++) c[j] = c[j] > 0.f ? c[j] : slope * c[j];
        }
        *reinterpret_cast<float4*>(&C[(size_t)gm * N + gn0]) = make_float4(c[0], c[1], c[2], c[3]);
        *reinterpret_cast<float4*>(&C[(size_t)gm * N + gn1]) = make_float4(c[4], c[5], c[6], c[7]);
    }
}

// ---------------- precompute attention dots ----------------
template<int H>
__global__ void attdot_kernel(const float* __restrict__ feat,
                              const float* __restrict__ attL, const float* __restrict__ attR,
                              float* __restrict__ aldot, float* __restrict__ ardot) {
    int warp = (blockIdx.x * blockDim.x + threadIdx.x) >> 5;
    int lane = threadIdx.x & 31;
    if (warp >= N_NODES * H) return;
    int nid = warp / H, h = warp % H;
    float4 x = reinterpret_cast<const float4*>(feat + ((size_t)nid * H + h) * NHID)[lane];
    float4 aL = reinterpret_cast<const float4*>(attL + h * NHID)[lane];
    float4 aR = reinterpret_cast<const float4*>(attR + h * NHID)[lane];
    float al = x.x * aL.x + x.y * aL.y + x.z * aL.z + x.w * aL.w;
    float ar = x.x * aR.x + x.y * aR.y + x.z * aR.z + x.w * aR.w;
    #pragma unroll
    for (int o = 16; o; o >>= 1) {
        al += __shfl_xor_sync(0xffffffffu, al, o);
        ar += __shfl_xor_sync(0xffffffffu, ar, o);
    }
    if (lane == 0) { aldot[warp] = al; ardot[warp] = ar; }
}

// ---------------- SuperGAT aggregation ----------------
template<int H>
__global__ void agg_kernel(const float* __restrict__ feat,
                           const float* __restrict__ aldot, const float* __restrict__ ardot,
                           const float* __restrict__ bias,
                           const int* __restrict__ rowptr, const int* __restrict__ esrc,
                           float* __restrict__ out, float out_slope) {
    const int C = NHID;
    int warp = (blockIdx.x * blockDim.x + threadIdx.x) >> 5;
    int lane = threadIdx.x & 31;
    if (warp >= N_NODES * H) return;
    int nid = warp / H;
    int h   = warp % H;

    float4 xi = reinterpret_cast<const float4*>(feat + ((size_t)nid * H + h) * C)[lane];
    float ar = ardot[warp];

    float m = -INFINITY, s = 0.f;
    float4 acc = make_float4(0.f, 0.f, 0.f, 0.f);

    int e0 = rowptr[nid], e1 = rowptr[nid + 1];
    int e = e0;
    for (; e + 1 < e1; e += 2) {
        int s1 = esrc[e], s2 = esrc[e + 1];
        float4 xj1 = reinterpret_cast<const float4*>(feat + ((size_t)s1 * H + h) * C)[lane];
        float4 xj2 = reinterpret_cast<const float4*>(feat + ((size_t)s2 * H + h) * C)[lane];
        float lg1 = xi.x * xj1.x + xi.y * xj1.y + xi.z * xj1.z + xi.w * xj1.w;
        float lg2 = xi.x * xj2.x + xi.y * xj2.y + xi.z * xj2.z + xi.w * xj2.w;
        #pragma unroll
        for (int o = 16; o; o >>= 1) {
            lg1 += __shfl_xor_sync(0xffffffffu, lg1, o);
            lg2 += __shfl_xor_sync(0xffffffffu, lg2, o);
        }
        float al1 = aldot[s1 * H + h], al2 = aldot[s2 * H + h];
        float a1 = (al1 + ar) * (1.f / (1.f + expf(-lg1)));
        float a2 = (al2 + ar) * (1.f / (1.f + expf(-lg2)));
        a1 = a1 > 0.f ? a1 : 0.2f * a1;
        a2 = a2 > 0.f ? a2 : 0.2f * a2;
        float mn = fmaxf(m, fmaxf(a1, a2));
        float scale = expf(m - mn);
        float w1 = expf(a1 - mn), w2 = expf(a2 - mn);
        s = s * scale + w1 + w2;
        acc.x = acc.x * scale + w1 * xj1.x + w2 * xj2.x;
        acc.y = acc.y * scale + w1 * xj1.y + w2 * xj2.y;
        acc.z = acc.z * scale + w1 * xj1.z + w2 * xj2.z;
        acc.w = acc.w * scale + w1 * xj1.w + w2 * xj2.w;
        m = mn;
    }
    for (; e < e1; e++) {
        int sn = esrc[e];
        float4 xj = reinterpret_cast<const float4*>(feat + ((size_t)sn * H + h) * C)[lane];
        float lg = xi.x * xj.x + xi.y * xj.y + xi.z * xj.z + xi.w * xj.w;
        #pragma unroll
        for (int o = 16; o; o >>= 1) lg += __shfl_xor_sync(0xffffffffu, lg, o);
        float al = aldot[sn * H + h];
        float a = (al + ar) * (1.f / (1.f + expf(-lg)));
        a = a > 0.f ? a : 0.2f * a;
        float mn = fmaxf(m, a);
        float scale = expf(m - mn);
        float w = expf(a - mn);
        s = s * scale + w;
        acc.x = acc.x * scale + w * xj.x;
        acc.y = acc.y * scale + w * xj.y;
        acc.z = acc.z * scale + w * xj.z;
        acc.w = acc.w * scale + w * xj.w;
        m = mn;
    }
    float inv = 1.f / (s + 1e-16f);
    float4 b4 = reinterpret_cast<const float4*>(bias + h * C)[lane];
    float4 r;
    r.x = acc.x * inv + b4.x; r.x = r.x > 0.f ? r.x : out_slope * r.x;
    r.y = acc.y * inv + b4.y; r.y = r.y > 0.f ? r.y : out_slope * r.y;
    r.z = acc.z * inv + b4.z; r.z = r.z > 0.f ? r.z : out_slope * r.z;
    r.w = acc.w * inv + b4.w; r.w = r.w > 0.f ? r.w : out_slope * r.w;
    reinterpret_cast<float4*>(out + ((size_t)nid * H + h) * C)[lane] = r;
}

// ---------------- graph pooling ----------------
__global__ void pool_init_kernel(float* pool) {
    int i = blockIdx.x * blockDim.x + threadIdx.x;
    if (i < NUM_GRAPHS * NHID) pool[i] = -FLT_MAX;
}

__device__ __forceinline__ void atomicMaxF(float* a, float v) {
    if (v >= 0.f) atomicMax((int*)a, __float_as_int(v));
    else          atomicMin((unsigned int*)a, __float_as_uint(v));
}

__global__ void pool_max_kernel(const float* __restrict__ x, const int* __restrict__ batch,
                                float* __restrict__ pool) {
    int i = blockIdx.x * blockDim.x + threadIdx.x;
    if (i >= N_NODES * NHID) return;
    int n = i / NHID, c = i % NHID;
    atomicMaxF(&pool[batch[n] * NHID + c], x[i]);
}

// ---------------- launch ----------------
static inline float* symf(const void* sym) {
    void* p = nullptr; cudaGetSymbolAddress(&p, sym); return (float*)p;
}
static inline int* symi(const void* sym) {
    void* p = nullptr; cudaGetSymbolAddress(&p, sym); return (int*)p;
}

extern "C" void kernel_launch(void* const* d_in, const int* in_sizes, int n_in,
                              void* d_out, int out_size) {
    const float* x      = (const float*)d_in[0];
    const int*   eidx   = (const int*)  d_in[1];
    const int*   batch  = (const int*)  d_in[2];
    const float* fc1_w  = (const float*)d_in[3];
    const float* fc1_b  = (const float*)d_in[4];
    const float* w1     = (const float*)d_in[5];
    const float* att_l1 = (const float*)d_in[6];
    const float* att_r1 = (const float*)d_in[7];
    const float* b1     = (const float*)d_in[8];
    const float* w2     = (const float*)d_in[9];
    const float* att_l2 = (const float*)d_in[10];
    const float* att_r2 = (const float*)d_in[11];
    const float* b2     = (const float*)d_in[12];
    const float* fc2_w  = (const float*)d_in[13];
    const float* fc2_b  = (const float*)d_in[14];
    float* out = (float*)d_out;

    const int* e_src = eidx;
    const int* e_dst = eidx + N_EDGES;

    float* h0 = symf(g_h0); float* f1 = symf(g_f1); float* o1 = symf(g_o1);
    float* f2 = symf(g_f2); float* o2 = symf(g_o2); float* pool = symf(g_pool);
    float* aldot = symf(g_aldot); float* ardot = symf(g_ardot);
    int* deg = symi(g_deg); int* rowptr = symi(g_rowptr);
    int* cursor = symi(g_cursor); int* esrc = symi(g_esrc);

    zero_int_kernel<<<(N_NODES + 255) / 256, 256>>>(deg, N_NODES);                     // 0
    hist_kernel<<<(N_EDGES + 255) / 256, 256>>>(e_dst, deg, N_EDGES);                  // 1

    // GEMM1: h0 = leaky(x @ fc1_w + fc1_b)  [20000,300]x[300,128]  -> BM=64 (313 blocks)
    {
        dim3 grid(NHID / 128, (N_NODES + 63) / 64);
        gemm2x_kernel<64, 128><<<grid, 128>>>(x, fc1_w, fc1_b, h0, N_NODES, NHID, N_IN, 0.01f, 1); // 2
    }
    // GEMM2: f1 = h0 @ w1   [20000,128]x[128,512]  (profiled slot, unchanged config)
    {
        dim3 grid(HEADS * NHID / 128, (N_NODES + 127) / 128);
        gemm2x_kernel<128, 128><<<grid, 256>>>(h0, w1, nullptr, f1, N_NODES, HEADS * NHID, NHID, 0.f, 0); // 3
    }

    scan_kernel<<<1, 1024>>>(deg, rowptr, cursor);                                     // 4
    scatter_kernel<<<(N_EDGES + 255) / 256, 256>>>(e_src, e_dst, cursor, esrc, N_EDGES); // 5

    {
        int warps = N_NODES * HEADS;
        attdot_kernel<HEADS><<<(warps * 32 + 255) / 256, 256>>>(f1, att_l1, att_r1, aldot, ardot); // 6
    }
    {
        int warps = N_NODES * HEADS;
        agg_kernel<HEADS><<<(warps * 32 + 255) / 256, 256>>>(f1, aldot, ardot, b1,
                                                             rowptr, esrc, o1, 0.01f); // 7
    }
    // GEMM3: f2 = o1 @ w2   [20000,512]x[512,128]  -> BM=64 (313 blocks)
    {
        dim3 grid(NHID / 128, (N_NODES + 63) / 64);
        gemm2x_kernel<64, 128><<<grid, 128>>>(o1, w2, nullptr, f2, N_NODES, NHID, HEADS * NHID, 0.f, 0); // 8
    }
    {
        int warps = N_NODES;
        attdot_kernel<1><<<(warps * 32 + 255) / 256, 256>>>(f2, att_l2, att_r2, aldot, ardot); // 9
    }
    {
        int warps = N_NODES;
        agg_kernel<1><<<(warps * 32 + 255) / 256, 256>>>(f2, aldot, ardot, b2,
                                                         rowptr, esrc, o2, 0.01f);     // 10
    }
    pool_init_kernel<<<(NUM_GRAPHS * NHID + 255) / 256, 256>>>(pool);                  // 11
    pool_max_kernel<<<(N_NODES * NHID + 255) / 256, 256>>>(o2, batch, pool);           // 12

    // GEMM4: out = pool @ fc2_w + fc2_b   [128,128]x[128,768]
    {
        dim3 grid(NOUT / 128, (NUM_GRAPHS + 127) / 128);
        gemm2x_kernel<128, 128><<<grid, 256>>>(pool, fc2_w, fc2_b, out, NUM_GRAPHS, NOUT, NHID, 0.f, 0); // 13
    }
}

// round 7
// speedup vs baseline: 1.5096x; 1.3099x over previous
#include <cuda_runtime.h>
#include <cuda_bf16.h>
#include <cfloat>
#include <math.h>

// ---------------- problem constants ----------------
#define N_NODES   20000
#define N_EDGES   160000
#define N_IN      300
#define NHID      128
#define HEADS     4
#define NOUT      768
#define NUM_GRAPHS 128

typedef unsigned long long ull;

// ---------------- scratch ----------------
__device__ float g_h0[N_NODES * NHID];
__device__ float g_f1[N_NODES * HEADS * NHID];
__device__ float g_o1[N_NODES * HEADS * NHID];
__device__ float g_f2[N_NODES * NHID];
__device__ float g_o2[N_NODES * NHID];
__device__ float g_aldot[N_NODES * HEADS];
__device__ float g_ardot[N_NODES * HEADS];
__device__ int   g_deg[N_NODES];
__device__ int   g_rowptr[N_NODES + 1];
__device__ int   g_cursor[N_NODES];
__device__ int   g_esrc[N_EDGES];
__device__ float g_pool[NUM_GRAPHS * NHID];

// ---------------- tf32 helpers ----------------
__device__ __forceinline__ unsigned f2tf32(float f) {
    unsigned u;
    asm("cvt.rna.tf32.f32 %0, %1;" : "=r"(u) : "f"(f));
    return u;
}
__device__ __forceinline__ void mma_tf32(float& d0, float& d1, float& d2, float& d3,
                                         unsigned a0, unsigned a1, unsigned a2, unsigned a3,
                                         unsigned b0, unsigned b1) {
    asm("mma.sync.aligned.m16n8k8.row.col.f32.tf32.tf32.f32 "
        "{%0,%1,%2,%3}, {%4,%5,%6,%7}, {%8,%9}, {%0,%1,%2,%3};"
        : "+f"(d0), "+f"(d1), "+f"(d2), "+f"(d3)
        : "r"(a0), "r"(a1), "r"(a2), "r"(a3), "r"(b0), "r"(b1));
}

// ---------------- CSR build ----------------
__global__ void zero_int_kernel(int* p, int n) {
    int i = blockIdx.x * blockDim.x + threadIdx.x;
    if (i < n) p[i] = 0;
}

__global__ void hist_kernel(const int* __restrict__ dst, int* __restrict__ deg, int E) {
    int i = blockIdx.x * blockDim.x + threadIdx.x;
    if (i < E) atomicAdd(&deg[dst[i]], 1);
}

__global__ void scan_kernel(const int* __restrict__ deg, int* __restrict__ rowptr,
                            int* __restrict__ cursor) {
    __shared__ int sh[1024];
    const int PER = 20;
    int tid = threadIdx.x;
    int base = tid * PER;
    int loc[PER];
    int s = 0;
    #pragma unroll
    for (int i = 0; i < PER; i++) {
        int idx = base + i;
        int v = (idx < N_NODES) ? deg[idx] : 0;
        loc[i] = s;
        s += v;
    }
    sh[tid] = s;
    __syncthreads();
    #pragma unroll
    for (int off = 1; off < 1024; off <<= 1) {
        int t = (tid >= off) ? sh[tid - off] : 0;
        __syncthreads();
        sh[tid] += t;
        __syncthreads();
    }
    int prev = (tid > 0) ? sh[tid - 1] : 0;
    #pragma unroll
    for (int i = 0; i < PER; i++) {
        int idx = base + i;
        if (idx < N_NODES) {
            int v = prev + loc[i];
            rowptr[idx] = v;
            cursor[idx] = v;
        }
    }
    if (tid == 1023) rowptr[N_NODES] = sh[1023];
}

__global__ void scatter_kernel(const int* __restrict__ src, const int* __restrict__ dst,
                               int* __restrict__ cursor, int* __restrict__ esrc, int E) {
    int i = blockIdx.x * blockDim.x + threadIdx.x;
    if (i < E) {
        int d = dst[i];
        int p = atomicAdd(&cursor[d], 1);
        esrc[p] = src[i];
    }
}

// ---------------- tf32 tensor-core GEMM ----------------
// C[M,N] = act(A[M,K] @ B[K,N] + bias). BM=BN=128, BK=16 (2 k8 steps / tile).
// 256 threads = 8 warps (2x4); warp tile 64x32 = 4 m-frags x 4 n-frags of m16n8k8.
// A in smem [16][136] (pad 8 -> conflict-free fragment gathers).
// B in fragment-permuted smem: (kb,nb) groups of 33 float2 (1 LDS.64 per n-frag).
__global__ __launch_bounds__(256, 2)
void gemm_tf32_kernel(const float* __restrict__ A, const float* __restrict__ B,
                      const float* __restrict__ bias, float* __restrict__ C,
                      int M, int N, int K, float slope, int act) {
    const int BM = 128, BN = 128, BK = 16;
    const int ASTR = 136;                    // 128 + 8 pad
    __shared__ unsigned As[BK * ASTR];       // tf32 bits, [k][m]
    __shared__ unsigned Bs[2 * 16 * 33 * 2]; // (kb*16+nb) groups, 33 float2 each

    int tid = threadIdx.x;
    int lane = tid & 31;
    int wid = tid >> 5;
    int warpM = wid >> 2;                    // 0..1
    int warpN = wid & 3;                     // 0..3
    int bm = blockIdx.y * BM, bn = blockIdx.x * BN;
    int g = lane >> 2, c = lane & 3;

    float acc[4][4][4];
    #pragma unroll
    for (int mi = 0; mi < 4; mi++)
        #pragma unroll
        for (int ni = 0; ni < 4; ni++)
            #pragma unroll
            for (int r = 0; r < 4; r++) acc[mi][ni][r] = 0.f;

    // A loader: row la_m, k-cols la_k..la_k+7 (2 float4)
    int la_m = tid >> 1;
    int la_k = (tid & 1) * 8;
    int gmA = bm + la_m;
    // B loader: row lbk (0..15), cols lbn..lbn+7 (2 float4)
    int lbk = tid >> 4;
    int lbn = (tid & 15) * 8;
    int b_kb = lbk >> 3;
    int b_c = lbk & 3;
    int b_half = (lbk & 7) >> 2;
    int b_nb = tid & 15;

    for (int k0 = 0; k0 < K; k0 += BK) {
        // ---- stage A tile (convert to tf32) ----
        #pragma unroll
        for (int gg = 0; gg < 8; gg += 4) {
            int kk = la_k + gg;
            int gk = k0 + kk;
            float4 v = make_float4(0.f, 0.f, 0.f, 0.f);
            if (gmA < M && gk < K)
                v = *reinterpret_cast<const float4*>(&A[(size_t)gmA * K + gk]);
            As[(kk + 0) * ASTR + la_m] = f2tf32(v.x);
            As[(kk + 1) * ASTR + la_m] = f2tf32(v.y);
            As[(kk + 2) * ASTR + la_m] = f2tf32(v.z);
            As[(kk + 3) * ASTR + la_m] = f2tf32(v.w);
        }
        // ---- stage B tile (fragment-permuted) ----
        {
            int gk = k0 + lbk;
            float4 v0 = make_float4(0.f, 0.f, 0.f, 0.f);
            float4 v1 = make_float4(0.f, 0.f, 0.f, 0.f);
            if (gk < K) {
                v0 = *reinterpret_cast<const float4*>(&B[(size_t)gk * N + bn + lbn]);
                v1 = *reinterpret_cast<const float4*>(&B[(size_t)gk * N + bn + lbn + 4]);
            }
            float vv[8] = {v0.x, v0.y, v0.z, v0.w, v1.x, v1.y, v1.z, v1.w};
            int grp = b_kb * 16 + b_nb;
            #pragma unroll
            for (int j = 0; j < 8; j++) {
                int u = grp * 33 + j * 4 + b_c;
                Bs[2 * u + b_half] = f2tf32(vv[j]);
            }
        }
        __syncthreads();

        // ---- compute 2 k8 steps ----
        #pragma unroll
        for (int kb = 0; kb < 2; kb++) {
            unsigned af[4][4];
            int r0 = (kb * 8 + c) * ASTR;
            int r1 = (kb * 8 + c + 4) * ASTR;
            #pragma unroll
            for (int mi = 0; mi < 4; mi++) {
                int m0 = warpM * 64 + mi * 16;
                af[mi][0] = As[r0 + m0 + g];
                af[mi][1] = As[r0 + m0 + g + 8];
                af[mi][2] = As[r1 + m0 + g];
                af[mi][3] = As[r1 + m0 + g + 8];
            }
            unsigned bf[4][2];
            #pragma unroll
            for (int ni = 0; ni < 4; ni++) {
                int grp = kb * 16 + warpN * 4 + ni;
                uint2 t = *reinterpret_cast<const uint2*>(&Bs[2 * (grp * 33 + lane)]);
                bf[ni][0] = t.x;
                bf[ni][1] = t.y;
            }
            #pragma unroll
            for (int mi = 0; mi < 4; mi++)
                #pragma unroll
                for (int ni = 0; ni < 4; ni++)
                    mma_tf32(acc[mi][ni][0], acc[mi][ni][1], acc[mi][ni][2], acc[mi][ni][3],
                             af[mi][0], af[mi][1], af[mi][2], af[mi][3],
                             bf[ni][0], bf[ni][1]);
        }
        __syncthreads();
    }

    // ---- epilogue ----
    #pragma unroll
    for (int mi = 0; mi < 4; mi++) {
        int row0 = bm + warpM * 64 + mi * 16 + g;
        #pragma unroll
        for (int ni = 0; ni < 4; ni++) {
            int col = bn + warpN * 32 + ni * 8 + c * 2;
            float bv0 = bias ? bias[col] : 0.f;
            float bv1 = bias ? bias[col + 1] : 0.f;
            if (row0 < M) {
                float x0 = acc[mi][ni][0] + bv0;
                float x1 = acc[mi][ni][1] + bv1;
                if (act) {
                    x0 = x0 > 0.f ? x0 : slope * x0;
                    x1 = x1 > 0.f ? x1 : slope * x1;
                }
                *reinterpret_cast<float2*>(&C[(size_t)row0 * N + col]) = make_float2(x0, x1);
            }
            int row1 = row0 + 8;
            if (row1 < M) {
                float x2 = acc[mi][ni][2] + bv0;
                float x3 = acc[mi][ni][3] + bv1;
                if (act) {
                    x2 = x2 > 0.f ? x2 : slope * x2;
                    x3 = x3 > 0.f ? x3 : slope * x3;
                }
                *reinterpret_cast<float2*>(&C[(size_t)row1 * N + col]) = make_float2(x2, x3);
            }
        }
    }
}

// ---------------- precompute attention dots ----------------
template<int H>
__global__ void attdot_kernel(const float* __restrict__ feat,
                              const float* __restrict__ attL, const float* __restrict__ attR,
                              float* __restrict__ aldot, float* __restrict__ ardot) {
    int warp = (blockIdx.x * blockDim.x + threadIdx.x) >> 5;
    int lane = threadIdx.x & 31;
    if (warp >= N_NODES * H) return;
    int nid = warp / H, h = warp % H;
    float4 x = reinterpret_cast<const float4*>(feat + ((size_t)nid * H + h) * NHID)[lane];
    float4 aL = reinterpret_cast<const float4*>(attL + h * NHID)[lane];
    float4 aR = reinterpret_cast<const float4*>(attR + h * NHID)[lane];
    float al = x.x * aL.x + x.y * aL.y + x.z * aL.z + x.w * aL.w;
    float ar = x.x * aR.x + x.y * aR.y + x.z * aR.z + x.w * aR.w;
    #pragma unroll
    for (int o = 16; o; o >>= 1) {
        al += __shfl_xor_sync(0xffffffffu, al, o);
        ar += __shfl_xor_sync(0xffffffffu, ar, o);
    }
    if (lane == 0) { aldot[warp] = al; ardot[warp] = ar; }
}

// ---------------- SuperGAT aggregation ----------------
template<int H>
__global__ void agg_kernel(const float* __restrict__ feat,
                           const float* __restrict__ aldot, const float* __restrict__ ardot,
                           const float* __restrict__ bias,
                           const int* __restrict__ rowptr, const int* __restrict__ esrc,
                           float* __restrict__ out, float out_slope) {
    const int C = NHID;
    int warp = (blockIdx.x * blockDim.x + threadIdx.x) >> 5;
    int lane = threadIdx.x & 31;
    if (warp >= N_NODES * H) return;
    int nid = warp / H;
    int h   = warp % H;

    float4 xi = reinterpret_cast<const float4*>(feat + ((size_t)nid * H + h) * C)[lane];
    float ar = ardot[warp];

    float m = -INFINITY, s = 0.f;
    float4 acc = make_float4(0.f, 0.f, 0.f, 0.f);

    int e0 = rowptr[nid], e1 = rowptr[nid + 1];
    int e = e0;
    for (; e + 1 < e1; e += 2) {
        int s1 = esrc[e], s2 = esrc[e + 1];
        float4 xj1 = reinterpret_cast<const float4*>(feat + ((size_t)s1 * H + h) * C)[lane];
        float4 xj2 = reinterpret_cast<const float4*>(feat + ((size_t)s2 * H + h) * C)[lane];
        float lg1 = xi.x * xj1.x + xi.y * xj1.y + xi.z * xj1.z + xi.w * xj1.w;
        float lg2 = xi.x * xj2.x + xi.y * xj2.y + xi.z * xj2.z + xi.w * xj2.w;
        #pragma unroll
        for (int o = 16; o; o >>= 1) {
            lg1 += __shfl_xor_sync(0xffffffffu, lg1, o);
            lg2 += __shfl_xor_sync(0xffffffffu, lg2, o);
        }
        float al1 = aldot[s1 * H + h], al2 = aldot[s2 * H + h];
        float a1 = (al1 + ar) * (1.f / (1.f + expf(-lg1)));
        float a2 = (al2 + ar) * (1.f / (1.f + expf(-lg2)));
        a1 = a1 > 0.f ? a1 : 0.2f * a1;
        a2 = a2 > 0.f ? a2 : 0.2f * a2;
        float mn = fmaxf(m, fmaxf(a1, a2));
        float scale = expf(m - mn);
        float w1 = expf(a1 - mn), w2 = expf(a2 - mn);
        s = s * scale + w1 + w2;
        acc.x = acc.x * scale + w1 * xj1.x + w2 * xj2.x;
        acc.y = acc.y * scale + w1 * xj1.y + w2 * xj2.y;
        acc.z = acc.z * scale + w1 * xj1.z + w2 * xj2.z;
        acc.w = acc.w * scale + w1 * xj1.w + w2 * xj2.w;
        m = mn;
    }
    for (; e < e1; e++) {
        int sn = esrc[e];
        float4 xj = reinterpret_cast<const float4*>(feat + ((size_t)sn * H + h) * C)[lane];
        float lg = xi.x * xj.x + xi.y * xj.y + xi.z * xj.z + xi.w * xj.w;
        #pragma unroll
        for (int o = 16; o; o >>= 1) lg += __shfl_xor_sync(0xffffffffu, lg, o);
        float al = aldot[sn * H + h];
        float a = (al + ar) * (1.f / (1.f + expf(-lg)));
        a = a > 0.f ? a : 0.2f * a;
        float mn = fmaxf(m, a);
        float scale = expf(m - mn);
        float w = expf(a - mn);
        s = s * scale + w;
        acc.x = acc.x * scale + w * xj.x;
        acc.y = acc.y * scale + w * xj.y;
        acc.z = acc.z * scale + w * xj.z;
        acc.w = acc.w * scale + w * xj.w;
        m = mn;
    }
    float inv = 1.f / (s + 1e-16f);
    float4 b4 = reinterpret_cast<const float4*>(bias + h * C)[lane];
    float4 r;
    r.x = acc.x * inv + b4.x; r.x = r.x > 0.f ? r.x : out_slope * r.x;
    r.y = acc.y * inv + b4.y; r.y = r.y > 0.f ? r.y : out_slope * r.y;
    r.z = acc.z * inv + b4.z; r.z = r.z > 0.f ? r.z : out_slope * r.z;
    r.w = acc.w * inv + b4.w; r.w = r.w > 0.f ? r.w : out_slope * r.w;
    reinterpret_cast<float4*>(out + ((size_t)nid * H + h) * C)[lane] = r;
}

// ---------------- graph pooling ----------------
__global__ void pool_init_kernel(float* pool) {
    int i = blockIdx.x * blockDim.x + threadIdx.x;
    if (i < NUM_GRAPHS * NHID) pool[i] = -FLT_MAX;
}

__device__ __forceinline__ void atomicMaxF(float* a, float v) {
    if (v >= 0.f) atomicMax((int*)a, __float_as_int(v));
    else          atomicMin((unsigned int*)a, __float_as_uint(v));
}

__global__ void pool_max_kernel(const float* __restrict__ x, const int* __restrict__ batch,
                                float* __restrict__ pool) {
    int i = blockIdx.x * blockDim.x + threadIdx.x;
    if (i >= N_NODES * NHID) return;
    int n = i / NHID, c = i % NHID;
    atomicMaxF(&pool[batch[n] * NHID + c], x[i]);
}

// ---------------- launch ----------------
static inline float* symf(const void* sym) {
    void* p = nullptr; cudaGetSymbolAddress(&p, sym); return (float*)p;
}
static inline int* symi(const void* sym) {
    void* p = nullptr; cudaGetSymbolAddress(&p, sym); return (int*)p;
}

extern "C" void kernel_launch(void* const* d_in, const int* in_sizes, int n_in,
                              void* d_out, int out_size) {
    const float* x      = (const float*)d_in[0];
    const int*   eidx   = (const int*)  d_in[1];
    const int*   batch  = (const int*)  d_in[2];
    const float* fc1_w  = (const float*)d_in[3];
    const float* fc1_b  = (const float*)d_in[4];
    const float* w1     = (const float*)d_in[5];
    const float* att_l1 = (const float*)d_in[6];
    const float* att_r1 = (const float*)d_in[7];
    const float* b1     = (const float*)d_in[8];
    const float* w2     = (const float*)d_in[9];
    const float* att_l2 = (const float*)d_in[10];
    const float* att_r2 = (const float*)d_in[11];
    const float* b2     = (const float*)d_in[12];
    const float* fc2_w  = (const float*)d_in[13];
    const float* fc2_b  = (const float*)d_in[14];
    float* out = (float*)d_out;

    const int* e_src = eidx;
    const int* e_dst = eidx + N_EDGES;

    float* h0 = symf(g_h0); float* f1 = symf(g_f1); float* o1 = symf(g_o1);
    float* f2 = symf(g_f2); float* o2 = symf(g_o2); float* pool = symf(g_pool);
    float* aldot = symf(g_aldot); float* ardot = symf(g_ardot);
    int* deg = symi(g_deg); int* rowptr = symi(g_rowptr);
    int* cursor = symi(g_cursor); int* esrc = symi(g_esrc);

    zero_int_kernel<<<(N_NODES + 255) / 256, 256>>>(deg, N_NODES);                     // 0
    hist_kernel<<<(N_EDGES + 255) / 256, 256>>>(e_dst, deg, N_EDGES);                  // 1

    // GEMM1: h0 = leaky(x @ fc1_w + fc1_b)  [20000,300]x[300,128]
    {
        dim3 grid(NHID / 128, (N_NODES + 127) / 128);
        gemm_tf32_kernel<<<grid, 256>>>(x, fc1_w, fc1_b, h0, N_NODES, NHID, N_IN, 0.01f, 1); // 2
    }
    // GEMM2: f1 = h0 @ w1   [20000,128]x[128,512]  (profiled slot 3)
    {
        dim3 grid(HEADS * NHID / 128, (N_NODES + 127) / 128);
        gemm_tf32_kernel<<<grid, 256>>>(h0, w1, nullptr, f1, N_NODES, HEADS * NHID, NHID, 0.f, 0); // 3
    }

    scan_kernel<<<1, 1024>>>(deg, rowptr, cursor);                                     // 4
    scatter_kernel<<<(N_EDGES + 255) / 256, 256>>>(e_src, e_dst, cursor, esrc, N_EDGES); // 5

    {
        int warps = N_NODES * HEADS;
        attdot_kernel<HEADS><<<(warps * 32 + 255) / 256, 256>>>(f1, att_l1, att_r1, aldot, ardot); // 6
    }
    {
        int warps = N_NODES * HEADS;
        agg_kernel<HEADS><<<(warps * 32 + 255) / 256, 256>>>(f1, aldot, ardot, b1,
                                                             rowptr, esrc, o1, 0.01f); // 7
    }
    // GEMM3: f2 = o1 @ w2   [20000,512]x[512,128]
    {
        dim3 grid(NHID / 128, (N_NODES + 127) / 128);
        gemm_tf32_kernel<<<grid, 256>>>(o1, w2, nullptr, f2, N_NODES, NHID, HEADS * NHID, 0.f, 0); // 8
    }
    {
        int warps = N_NODES;
        attdot_kernel<1><<<(warps * 32 + 255) / 256, 256>>>(f2, att_l2, att_r2, aldot, ardot); // 9
    }
    {
        int warps = N_NODES;
        agg_kernel<1><<<(warps * 32 + 255) / 256, 256>>>(f2, aldot, ardot, b2,
                                                         rowptr, esrc, o2, 0.01f);     // 10
    }
    pool_init_kernel<<<(NUM_GRAPHS * NHID + 255) / 256, 256>>>(pool);                  // 11
    pool_max_kernel<<<(N_NODES * NHID + 255) / 256, 256>>>(o2, batch, pool);           // 12

    // GEMM4: out = pool @ fc2_w + fc2_b   [128,128]x[128,768]
    {
        dim3 grid(NOUT / 128, (NUM_GRAPHS + 127) / 128);
        gemm_tf32_kernel<<<grid, 256>>>(pool, fc2_w, fc2_b, out, NUM_GRAPHS, NOUT, NHID, 0.f, 0); // 13
    }
}